// round 7
// baseline (speedup 1.0000x reference)
#include <cuda_runtime.h>
#include <cuda_fp16.h>
#include <cstdint>

#define DB 4
#define DT 256
#define DU 64
#define DENC 512
#define DPRED 640
#define DJ 640
#define DV 1024
#define BT (DB*DT)        // 1024 enc rows
#define BUROWS (DB*DU)    // 256 pred rows
#define M_TOTAL (BT*DU)   // 65536 joint rows

// ---------------- device scratch (no allocations allowed) ----------------
__device__ float  g_encP[BT * DJ];                 // 2.6 MB
__device__ float  g_predP[BUROWS * DJ];            // 0.66 MB
__device__ __half g_joint[(size_t)M_TOTAL * DJ];   // 84 MB
__device__ __half g_Wh[DV * DJ];                   // W_out^T [v][k], fp16

// ---------------- FFMA-only tanh (no MUFU) --------------------------------
__device__ __forceinline__ float fast_tanh(float x) {
    const float CL = 7.90531110763549805f;
    float xc = fminf(fmaxf(x, -CL), CL);
    float x2 = xc * xc;
    float np = fmaf(x2, -2.76076847742355e-16f, 2.00018790482477e-13f);
    np = fmaf(x2, np, -8.60467152213735e-11f);
    np = fmaf(x2, np,  5.12229709037114e-08f);
    np = fmaf(x2, np,  1.48572235717979e-05f);
    np = fmaf(x2, np,  6.37261928875436e-04f);
    np = fmaf(x2, np,  4.89352455891786e-03f);
    np = np * xc;
    float dp = fmaf(x2, 1.19825839466702e-06f, 1.18534705686654e-04f);
    dp = fmaf(x2, dp, 2.26843463243900e-03f);
    dp = fmaf(x2, dp, 4.89352518554385e-03f);
    float r = __uint_as_float(0x7EF311C4u - __float_as_uint(dp));
    r = r * fmaf(-dp, r, 2.0f);
    r = r * fmaf(-dp, r, 2.0f);
    r = r * fmaf(-dp, r, 2.0f);
    return np * r;
}

// ---------------- prep: projections (8 rows x 320 cols / block) + wconv ---
template<int K>
__device__ __forceinline__ void proj8(const float* __restrict__ X,
                                      const float* __restrict__ W,
                                      const float* __restrict__ bias,
                                      float* __restrict__ out, int r0, int joff,
                                      float* __restrict__ sx) {
    const int j = threadIdx.x + joff;
    for (int idx = threadIdx.x; idx < 8 * K; idx += 320) {
        int r = idx / K, k = idx - r * K;
        sx[k * 8 + r] = X[(size_t)(r0 + r) * K + k];
    }
    __syncthreads();
    float acc[8];
    float bj = bias[j];
#pragma unroll
    for (int r = 0; r < 8; r++) acc[r] = bj;
#pragma unroll 2
    for (int k0 = 0; k0 < K; k0 += 8) {
        float w[8];
#pragma unroll
        for (int q = 0; q < 8; q++) w[q] = W[(size_t)(k0 + q) * DJ + j];
#pragma unroll
        for (int q = 0; q < 8; q++) {
            float4 x0 = *(const float4*)&sx[(k0 + q) * 8];
            float4 x1 = *(const float4*)&sx[(k0 + q) * 8 + 4];
            acc[0] = fmaf(x0.x, w[q], acc[0]);
            acc[1] = fmaf(x0.y, w[q], acc[1]);
            acc[2] = fmaf(x0.z, w[q], acc[2]);
            acc[3] = fmaf(x0.w, w[q], acc[3]);
            acc[4] = fmaf(x1.x, w[q], acc[4]);
            acc[5] = fmaf(x1.y, w[q], acc[5]);
            acc[6] = fmaf(x1.z, w[q], acc[6]);
            acc[7] = fmaf(x1.w, w[q], acc[7]);
        }
    }
#pragma unroll
    for (int r = 0; r < 8; r++) out[(size_t)(r0 + r) * DJ + j] = acc[r];
}

// blocks [0,256): enc; [256,320): pred; [320,384): W_out transpose
__global__ void __launch_bounds__(320, 4) prep_kernel(const float* __restrict__ enc,
                                                      const float* __restrict__ W_enc,
                                                      const float* __restrict__ b_enc,
                                                      const float* __restrict__ pred,
                                                      const float* __restrict__ W_pred,
                                                      const float* __restrict__ b_pred,
                                                      const float* __restrict__ W_out) {
    __shared__ float sx[8 * DPRED];
    const int bx = blockIdx.x;
    if (bx < 256) {
        proj8<DENC>(enc, W_enc, b_enc, g_encP, (bx >> 1) * 8, (bx & 1) * 320, sx);
    } else if (bx < 320) {
        int bb = bx - 256;
        proj8<DPRED>(pred, W_pred, b_pred, g_predP, (bb >> 1) * 8, (bb & 1) * 320, sx);
    } else {
        for (int idx = (bx - 320) * 320 + threadIdx.x; idx < DV * DJ; idx += 64 * 320) {
            int k = idx >> 10;
            int v = idx & 1023;
            g_Wh[v * DJ + k] = __float2half_rn(W_out[idx]);
        }
    }
}

// ---------------- joint = tanh(encP + predP), tiled for L2 ---------------
// Block tile: 8 bt-rows x 32 u-rows; operands staged in smem (100KB).
#define TH_SMEM ((8*DJ + 32*DJ) * 4)
__global__ void __launch_bounds__(512) joint_tanh_kernel() {
    extern __shared__ float sm[];
    float* senc  = sm;               // 8 x 640
    float* spred = sm + 8 * DJ;      // 32 x 640
    const int bx  = blockIdx.x;      // 256 blocks
    const int bt0 = (bx >> 1) * 8;
    const int u0  = (bx & 1) * 32;
    const int b   = bt0 >> 8;
    const int tid = threadIdx.x;

    const float4* eg = (const float4*)(g_encP + (size_t)bt0 * DJ);
    const float4* pg = (const float4*)(g_predP + (size_t)(b * DU + u0) * DJ);
    for (int i = tid; i < 8 * DJ / 4; i += 512)  ((float4*)senc)[i]  = eg[i];
    for (int i = tid; i < 32 * DJ / 4; i += 512) ((float4*)spred)[i] = pg[i];
    __syncthreads();

    // 256 joint rows x 80 int4 chunks = 20480 items
#pragma unroll 4
    for (int it = 0; it < 40; it++) {
        int idx = it * 512 + tid;
        int rl = idx / 80;                 // 0..255
        int ch = idx - rl * 80;
        int bt_l = rl >> 5, u_l = rl & 31;
        const float4* e = (const float4*)&senc[bt_l * DJ + ch * 8];
        const float4* p = (const float4*)&spred[u_l * DJ + ch * 8];
        float4 e0 = e[0], e1 = e[1];
        float4 p0 = p[0], p1 = p[1];
        __half2 q0 = __floats2half2_rn(fast_tanh(e0.x + p0.x), fast_tanh(e0.y + p0.y));
        __half2 q1 = __floats2half2_rn(fast_tanh(e0.z + p0.z), fast_tanh(e0.w + p0.w));
        __half2 q2 = __floats2half2_rn(fast_tanh(e1.x + p1.x), fast_tanh(e1.y + p1.y));
        __half2 q3 = __floats2half2_rn(fast_tanh(e1.z + p1.z), fast_tanh(e1.w + p1.w));
        int4 v;
        v.x = *(int*)&q0; v.y = *(int*)&q1; v.z = *(int*)&q2; v.w = *(int*)&q3;
        size_t m = (size_t)(bt0 + bt_l) * DU + (u0 + u_l);
        *(int4*)(g_joint + m * DJ + ch * 8) = v;
    }
}

// ==================== GEMM: persistent-B + streaming A ====================
// Grid (8 N-groups, 18 M-groups) = 144 CTAs, 1/SM. Each CTA: B slice
// 128x640 fp16 (160KB smem, loaded once) + 4-stage x 16KB A ring; streams
// 28-29 M-blocks (128 rows) with a flat cross-block cp.async pipeline.
// 8 warps as 2(M)x4(N), warp tile 64x32.

#define SB_OFF 65536
#define GEMM_SMEM (SB_OFF + 128*DJ*2)   // 64KB ring + 160KB B = 229376

__device__ __forceinline__ uint32_t smem_u32(const void* p) {
    uint32_t a;
    asm("{ .reg .u64 t; cvta.to.shared.u64 t, %1; cvt.u32.u64 %0, t; }" : "=r"(a) : "l"(p));
    return a;
}
__device__ __forceinline__ uint32_t swz(uint32_t o) { return o ^ ((o >> 3) & 0x70); }
__device__ __forceinline__ void cp16(uint32_t dst, const void* src) {
    asm volatile("cp.async.cg.shared.global [%0], [%1], 16;" :: "r"(dst), "l"(src));
}
__device__ __forceinline__ void ldsm4(uint32_t& r0, uint32_t& r1, uint32_t& r2,
                                      uint32_t& r3, uint32_t a) {
    asm volatile("ldmatrix.sync.aligned.m8n8.x4.shared.b16 {%0,%1,%2,%3}, [%4];"
                 : "=r"(r0), "=r"(r1), "=r"(r2), "=r"(r3) : "r"(a));
}
__device__ __forceinline__ void mma16816(float c[4], const uint32_t a[4], const uint32_t b[2]) {
    asm volatile(
        "mma.sync.aligned.m16n8k16.row.col.f32.f16.f16.f32 "
        "{%0,%1,%2,%3}, {%4,%5,%6,%7}, {%8,%9}, {%0,%1,%2,%3};\n"
        : "+f"(c[0]), "+f"(c[1]), "+f"(c[2]), "+f"(c[3])
        : "r"(a[0]), "r"(a[1]), "r"(a[2]), "r"(a[3]), "r"(b[0]), "r"(b[1]));
}

__global__ void __launch_bounds__(256, 1) gemm_pb(const float* __restrict__ b_out,
                                                  float* __restrict__ out) {
    extern __shared__ char ds[];
    const uint32_t sbase = smem_u32(ds);
    const int tid  = threadIdx.x;
    const int warp = tid >> 5;
    const int lane = tid & 31;
    const int g = lane >> 2;
    const int t = lane & 3;
    const int wm = (warp >> 2) * 64;            // 2 M-warps
    const int wn = (warp & 3) * 32;             // 4 N-warps
    const int n0 = blockIdx.x * 128;
    const int by = blockIdx.y;
    const int mstart = 28 * by + (by < 8 ? by : 8);   // M-block start
    const int nblk   = (by < 8) ? 29 : 28;
    const int T = nblk * 10;                    // total k64 chunks to stream

    // ---- B: load entire 128x640 slice once (10 sub-tiles of 16KB) ----
    const __half* bG = g_Wh + (size_t)n0 * DJ;
#pragma unroll
    for (int q = 0; q < 40; q++) {
        int id = tid + 256 * q;                 // 10240 int4
        int kc = id >> 10, rem = id & 1023;
        int row = rem >> 3, c16 = rem & 7;
        cp16(sbase + SB_OFF + kc * 16384 + swz(row * 128 + c16 * 16),
             bG + (size_t)row * DJ + kc * 64 + c16 * 8);
    }
    asm volatile("cp.async.commit_group;" ::: "memory");

    // ---- bias preload to registers ----
    float bo[4][2];
#pragma unroll
    for (int j = 0; j < 4; j++) {
        int col = n0 + wn + j * 8 + 2 * t;
        bo[j][0] = b_out[col]; bo[j][1] = b_out[col + 1];
    }

    // ---- A chunk issuer: chunk tt -> (m-block tt/10, k64 chunk tt%10) ----
    auto issueA = [&](int tt) {
        int mb = tt / 10, c = tt - mb * 10;
        const __half* aG = g_joint + (size_t)(mstart + mb) * 128 * DJ + c * 64;
        uint32_t st = sbase + (tt & 3) * 16384;
#pragma unroll
        for (int q = 0; q < 4; q++) {
            int id = tid + 256 * q;
            int row = id >> 3, c16 = id & 7;
            cp16(st + swz(row * 128 + c16 * 16), aG + (size_t)row * DJ + c16 * 8);
        }
        asm volatile("cp.async.commit_group;" ::: "memory");
    };
    issueA(0); issueA(1); issueA(2);

    // ---- per-lane ldmatrix addressing ----
    const int rowA  = wm + (lane & 15);
    const uint32_t kbA  = (lane >> 4) * 16;
    const uint32_t xorA = (uint32_t)(rowA & 7) * 16;
    const int rowB  = wn + (lane & 7) + ((lane >> 4) << 3);
    const uint32_t kbB  = ((lane >> 3) & 1) * 16;
    const uint32_t xorB = (uint32_t)(lane & 7) * 16;

    float acc[4][4][4];
#pragma unroll
    for (int i = 0; i < 4; i++)
#pragma unroll
        for (int j = 0; j < 4; j++)
#pragma unroll
            for (int q = 0; q < 4; q++) acc[i][j][q] = 0.0f;

#pragma unroll 1
    for (int tt = 0; tt < T; tt++) {
        asm volatile("cp.async.wait_group 2;" ::: "memory");
        __syncthreads();
        if (tt + 3 < T) issueA(tt + 3);
        else asm volatile("cp.async.commit_group;" ::: "memory");

        const int mb = tt / 10, c = tt - mb * 10;
        const uint32_t stA = sbase + (tt & 3) * 16384;
        const uint32_t stB = sbase + SB_OFF + c * 16384;
#pragma unroll
        for (int ks = 0; ks < 4; ks++) {
            const uint32_t kb = ks * 32;
            uint32_t a[4][4];
#pragma unroll
            for (int i = 0; i < 4; i++)
                ldsm4(a[i][0], a[i][1], a[i][2], a[i][3],
                      stA + (uint32_t)(rowA + i * 16) * 128 + ((kb + kbA) ^ xorA));
            uint32_t b[4][2];
#pragma unroll
            for (int jp = 0; jp < 2; jp++) {
                uint32_t r0, r1, r2, r3;
                ldsm4(r0, r1, r2, r3,
                      stB + (uint32_t)(rowB + jp * 16) * 128 + ((kb + kbB) ^ xorB));
                b[2*jp][0] = r0; b[2*jp][1] = r1;
                b[2*jp+1][0] = r2; b[2*jp+1][1] = r3;
            }
#pragma unroll
            for (int i = 0; i < 4; i++)
#pragma unroll
                for (int j = 0; j < 4; j++)
                    mma16816(acc[i][j], a[i], b[j]);
        }

        if (c == 9) {       // M-block complete: bias + clamp + store, reset acc
            const int m0 = (mstart + mb) * 128;
#pragma unroll
            for (int j = 0; j < 4; j++) {
                int col = n0 + wn + j * 8 + 2 * t;
#pragma unroll
                for (int i = 0; i < 4; i++) {
                    int r0 = m0 + wm + i * 16 + g;
                    float2 v0, v1;
                    v0.x = fminf(fmaxf(acc[i][j][0] + bo[j][0], -15.0f), 15.0f);
                    v0.y = fminf(fmaxf(acc[i][j][1] + bo[j][1], -15.0f), 15.0f);
                    v1.x = fminf(fmaxf(acc[i][j][2] + bo[j][0], -15.0f), 15.0f);
                    v1.y = fminf(fmaxf(acc[i][j][3] + bo[j][1], -15.0f), 15.0f);
                    *(float2*)(out + (size_t)r0 * DV + col)       = v0;
                    *(float2*)(out + (size_t)(r0 + 8) * DV + col) = v1;
#pragma unroll
                    for (int q = 0; q < 4; q++) acc[i][j][q] = 0.0f;
                }
            }
        }
    }
}

// ---------------- launch ---------------------------------------------------
extern "C" void kernel_launch(void* const* d_in, const int* in_sizes, int n_in,
                              void* d_out, int out_size) {
    const float* enc    = (const float*)d_in[0];
    const float* pred   = (const float*)d_in[1];
    const float* W_enc  = (const float*)d_in[2];
    const float* b_enc  = (const float*)d_in[3];
    const float* W_pred = (const float*)d_in[4];
    const float* b_pred = (const float*)d_in[5];
    const float* W_out  = (const float*)d_in[6];
    const float* b_out  = (const float*)d_in[7];
    float* out = (float*)d_out;

    cudaFuncSetAttribute(gemm_pb, cudaFuncAttributeMaxDynamicSharedMemorySize, GEMM_SMEM);
    cudaFuncSetAttribute(joint_tanh_kernel, cudaFuncAttributeMaxDynamicSharedMemorySize, TH_SMEM);

    prep_kernel<<<384, 320>>>(enc, W_enc, b_enc, pred, W_pred, b_pred, W_out);
    joint_tanh_kernel<<<256, 512, TH_SMEM>>>();
    gemm_pb<<<dim3(8, 18), 256, GEMM_SMEM>>>(b_out, out);
}

// round 8
// speedup vs baseline: 1.2509x; 1.2509x over previous
#include <cuda_runtime.h>
#include <cuda_fp16.h>
#include <cstdint>

#define DB 4
#define DT 256
#define DU 64
#define DENC 512
#define DPRED 640
#define DJ 640
#define DV 1024
#define BT (DB*DT)        // 1024 enc rows
#define BUROWS (DB*DU)    // 256 pred rows
#define M_TOTAL (BT*DU)   // 65536 joint rows

// ---------------- device scratch (no allocations allowed) ----------------
__device__ float  g_encP[BT * DJ];                 // 2.6 MB
__device__ float  g_predP[BUROWS * DJ];            // 0.66 MB
__device__ __half g_joint[(size_t)M_TOTAL * DJ];   // 84 MB
__device__ __half g_Wh[DV * DJ];                   // W_out^T [v][k], fp16

// ---------------- tanh via MUFU.TANH (sm_75+ family-legal) ----------------
__device__ __forceinline__ float tanha(float x) {
    float y;
    asm("tanh.approx.f32 %0, %1;" : "=f"(y) : "f"(x));
    return y;
}

// ---------------- prep: projections + wconv -------------------------------
// 8 rows x 320 cols per block; sx transposed [k][r]; W prefetched 16 k-rows
// ahead in registers (ping-pong) so L2 latency is covered by FMA issue.
template<int K>
__device__ __forceinline__ void proj8(const float* __restrict__ X,
                                      const float* __restrict__ W,
                                      const float* __restrict__ bias,
                                      float* __restrict__ out, int r0, int joff,
                                      float* __restrict__ sx) {
    const int j = threadIdx.x + joff;
    for (int idx = threadIdx.x; idx < 8 * K; idx += 320) {
        int r = idx / K, k = idx - r * K;
        sx[k * 8 + r] = X[(size_t)(r0 + r) * K + k];
    }
    __syncthreads();
    float acc[8];
    float bj = bias[j];
#pragma unroll
    for (int r = 0; r < 8; r++) acc[r] = bj;

    float wc[16], wn[16];
#pragma unroll
    for (int q = 0; q < 16; q++) wc[q] = W[(size_t)q * DJ + j];

#define FMA_BATCH(WREG, KBASE)                                          \
    _Pragma("unroll")                                                   \
    for (int q = 0; q < 16; q++) {                                      \
        float4 x0 = *(const float4*)&sx[((KBASE) + q) * 8];             \
        float4 x1 = *(const float4*)&sx[((KBASE) + q) * 8 + 4];         \
        acc[0] = fmaf(x0.x, WREG[q], acc[0]);                           \
        acc[1] = fmaf(x0.y, WREG[q], acc[1]);                           \
        acc[2] = fmaf(x0.z, WREG[q], acc[2]);                           \
        acc[3] = fmaf(x0.w, WREG[q], acc[3]);                           \
        acc[4] = fmaf(x1.x, WREG[q], acc[4]);                           \
        acc[5] = fmaf(x1.y, WREG[q], acc[5]);                           \
        acc[6] = fmaf(x1.z, WREG[q], acc[6]);                           \
        acc[7] = fmaf(x1.w, WREG[q], acc[7]);                           \
    }

#pragma unroll 1
    for (int k0 = 0; k0 < K; k0 += 32) {
#pragma unroll
        for (int q = 0; q < 16; q++) wn[q] = W[(size_t)(k0 + 16 + q) * DJ + j];
        FMA_BATCH(wc, k0)
        if (k0 + 32 < K) {
#pragma unroll
            for (int q = 0; q < 16; q++) wc[q] = W[(size_t)(k0 + 32 + q) * DJ + j];
        }
        FMA_BATCH(wn, k0 + 16)
    }
#undef FMA_BATCH

#pragma unroll
    for (int r = 0; r < 8; r++) out[(size_t)(r0 + r) * DJ + j] = acc[r];
}

// blocks [0,256): enc; [256,320): pred; [320,384): W_out transpose
__global__ void __launch_bounds__(320, 3) prep_kernel(const float* __restrict__ enc,
                                                      const float* __restrict__ W_enc,
                                                      const float* __restrict__ b_enc,
                                                      const float* __restrict__ pred,
                                                      const float* __restrict__ W_pred,
                                                      const float* __restrict__ b_pred,
                                                      const float* __restrict__ W_out) {
    __shared__ float sx[8 * DPRED];
    const int bx = blockIdx.x;
    if (bx < 256) {
        proj8<DENC>(enc, W_enc, b_enc, g_encP, (bx >> 1) * 8, (bx & 1) * 320, sx);
    } else if (bx < 320) {
        int bb = bx - 256;
        proj8<DPRED>(pred, W_pred, b_pred, g_predP, (bb >> 1) * 8, (bb & 1) * 320, sx);
    } else {
        for (int idx = (bx - 320) * 320 + threadIdx.x; idx < DV * DJ; idx += 64 * 320) {
            int k = idx >> 10;
            int v = idx & 1023;
            g_Wh[v * DJ + k] = __float2half_rn(W_out[idx]);
        }
    }
}

// ---------------- joint = tanh(encP + predP) -> fp16 (flat, MUFU) --------
__global__ void __launch_bounds__(256) joint_tanh_kernel() {
    int idx = blockIdx.x * 256 + threadIdx.x;
    int m  = idx / 80;
    int kq = (idx - m * 80) * 8;
    int bt = m >> 6;
    int u  = m & 63;
    int b  = bt >> 8;
    const float4* e = (const float4*)(g_encP  + (size_t)bt * DJ + kq);
    const float4* p = (const float4*)(g_predP + (size_t)(b * DU + u) * DJ + kq);
    float4 e0 = e[0], e1 = e[1];
    float4 p0 = p[0], p1 = p[1];
    __half2 q0 = __floats2half2_rn(tanha(e0.x + p0.x), tanha(e0.y + p0.y));
    __half2 q1 = __floats2half2_rn(tanha(e0.z + p0.z), tanha(e0.w + p0.w));
    __half2 q2 = __floats2half2_rn(tanha(e1.x + p1.x), tanha(e1.y + p1.y));
    __half2 q3 = __floats2half2_rn(tanha(e1.z + p1.z), tanha(e1.w + p1.w));
    int4 v;
    v.x = *(int*)&q0; v.y = *(int*)&q1; v.z = *(int*)&q2; v.w = *(int*)&q3;
    *(int4*)(g_joint + (size_t)m * DJ + kq) = v;
}

// ==================== GEMM: ldmatrix + cp.async, 3-stage, 2 CTAs/SM ======
// (unchanged from Round 6 — measured ~217us)
#define BM 128
#define BN 128
#define BK 64
#define KTILES 10
#define ASZ (BM*BK*2)
#define BSZ (BN*BK*2)
#define STG (ASZ+BSZ)
#define STAGES 3
#define DYN_SMEM (STAGES*STG)

__device__ __forceinline__ uint32_t smem_u32(const void* p) {
    uint32_t a;
    asm("{ .reg .u64 t; cvta.to.shared.u64 t, %1; cvt.u32.u64 %0, t; }" : "=r"(a) : "l"(p));
    return a;
}
__device__ __forceinline__ uint32_t swz(uint32_t o) { return o ^ ((o >> 3) & 0x70); }
__device__ __forceinline__ void cp16(uint32_t dst, const void* src) {
    asm volatile("cp.async.cg.shared.global [%0], [%1], 16;" :: "r"(dst), "l"(src));
}
__device__ __forceinline__ void ldsm4(uint32_t& r0, uint32_t& r1, uint32_t& r2,
                                      uint32_t& r3, uint32_t a) {
    asm volatile("ldmatrix.sync.aligned.m8n8.x4.shared.b16 {%0,%1,%2,%3}, [%4];"
                 : "=r"(r0), "=r"(r1), "=r"(r2), "=r"(r3) : "r"(a));
}
__device__ __forceinline__ void mma16816(float c[4], const uint32_t a[4], const uint32_t b[2]) {
    asm volatile(
        "mma.sync.aligned.m16n8k16.row.col.f32.f16.f16.f32 "
        "{%0,%1,%2,%3}, {%4,%5,%6,%7}, {%8,%9}, {%0,%1,%2,%3};\n"
        : "+f"(c[0]), "+f"(c[1]), "+f"(c[2]), "+f"(c[3])
        : "r"(a[0]), "r"(a[1]), "r"(a[2]), "r"(a[3]), "r"(b[0]), "r"(b[1]));
}

__global__ void __launch_bounds__(128, 2) gemm_lm(const float* __restrict__ b_out,
                                                  float* __restrict__ out) {
    extern __shared__ char ds[];
    const uint32_t sbase = smem_u32(ds);
    const int tid  = threadIdx.x;
    const int warp = tid >> 5;
    const int lane = tid & 31;
    const int g = lane >> 2;
    const int t = lane & 3;
    const int wm = (warp >> 1) * 64;
    const int wn = (warp & 1) * 64;
    const int m0 = blockIdx.y * BM;
    const int n0 = blockIdx.x * BN;

    const __half* aG = g_joint + (size_t)m0 * DJ;
    const __half* bG = g_Wh    + (size_t)n0 * DJ;

    auto load_stage = [&](int s, int kt) {
        const uint32_t stA = sbase + s * STG;
        const uint32_t stB = stA + ASZ;
        const int koff = kt * BK;
#pragma unroll
        for (int q = 0; q < 8; q++) {
            int id = tid + 128 * q;
            int row = id >> 3, c = id & 7;
            cp16(stA + swz(row * 128 + c * 16), aG + (size_t)row * DJ + koff + c * 8);
        }
#pragma unroll
        for (int q = 0; q < 8; q++) {
            int id = tid + 128 * q;
            int row = id >> 3, c = id & 7;
            cp16(stB + swz(row * 128 + c * 16), bG + (size_t)row * DJ + koff + c * 8);
        }
        asm volatile("cp.async.commit_group;" ::: "memory");
    };

    const int rowA  = wm + (lane & 15);
    const uint32_t kbA  = (lane >> 4) * 16;
    const uint32_t xorA = (uint32_t)(rowA & 7) * 16;
    const int rowB  = wn + (lane & 7) + ((lane >> 4) << 3);
    const uint32_t kbB  = ((lane >> 3) & 1) * 16;
    const uint32_t xorB = (uint32_t)(lane & 7) * 16;

    float acc[4][8][4];
#pragma unroll
    for (int i = 0; i < 4; i++)
#pragma unroll
        for (int j = 0; j < 8; j++)
#pragma unroll
            for (int q = 0; q < 4; q++) acc[i][j][q] = 0.0f;

    auto compute = [&](int s) {
        const uint32_t stA = sbase + s * STG;
        const uint32_t stB = stA + ASZ;
#pragma unroll
        for (int ks = 0; ks < 4; ks++) {
            const uint32_t kb = ks * 32;
            uint32_t a[4][4];
#pragma unroll
            for (int i = 0; i < 4; i++)
                ldsm4(a[i][0], a[i][1], a[i][2], a[i][3],
                      stA + (uint32_t)(rowA + i * 16) * 128 + ((kb + kbA) ^ xorA));
            uint32_t b[8][2];
#pragma unroll
            for (int jp = 0; jp < 4; jp++) {
                uint32_t r0, r1, r2, r3;
                ldsm4(r0, r1, r2, r3,
                      stB + (uint32_t)(rowB + jp * 16) * 128 + ((kb + kbB) ^ xorB));
                b[2*jp][0] = r0; b[2*jp][1] = r1;
                b[2*jp+1][0] = r2; b[2*jp+1][1] = r3;
            }
#pragma unroll
            for (int i = 0; i < 4; i++)
#pragma unroll
                for (int j = 0; j < 8; j++)
                    mma16816(acc[i][j], a[i], b[j]);
        }
    };

    load_stage(0, 0);
    load_stage(1, 1);
#pragma unroll 1
    for (int kt = 0; kt < KTILES; kt++) {
        asm volatile("cp.async.wait_group 1;" ::: "memory");
        __syncthreads();
        if (kt + 2 < KTILES) load_stage((kt + 2) % 3, kt + 2);
        else asm volatile("cp.async.commit_group;" ::: "memory");
        compute(kt % 3);
    }

#pragma unroll
    for (int j = 0; j < 8; j++) {
        int col = n0 + wn + j * 8 + 2 * t;
        float bo0 = __ldg(b_out + col), bo1 = __ldg(b_out + col + 1);
#pragma unroll
        for (int i = 0; i < 4; i++) {
            int r0 = m0 + wm + i * 16 + g;
            float2 v0, v1;
            v0.x = fminf(fmaxf(acc[i][j][0] + bo0, -15.0f), 15.0f);
            v0.y = fminf(fmaxf(acc[i][j][1] + bo1, -15.0f), 15.0f);
            v1.x = fminf(fmaxf(acc[i][j][2] + bo0, -15.0f), 15.0f);
            v1.y = fminf(fmaxf(acc[i][j][3] + bo1, -15.0f), 15.0f);
            *(float2*)(out + (size_t)r0 * DV + col)       = v0;
            *(float2*)(out + (size_t)(r0 + 8) * DV + col) = v1;
        }
    }
}

// ---------------- launch ---------------------------------------------------
extern "C" void kernel_launch(void* const* d_in, const int* in_sizes, int n_in,
                              void* d_out, int out_size) {
    const float* enc    = (const float*)d_in[0];
    const float* pred   = (const float*)d_in[1];
    const float* W_enc  = (const float*)d_in[2];
    const float* b_enc  = (const float*)d_in[3];
    const float* W_pred = (const float*)d_in[4];
    const float* b_pred = (const float*)d_in[5];
    const float* W_out  = (const float*)d_in[6];
    const float* b_out  = (const float*)d_in[7];
    float* out = (float*)d_out;

    cudaFuncSetAttribute(gemm_lm, cudaFuncAttributeMaxDynamicSharedMemorySize, DYN_SMEM);

    prep_kernel<<<384, 320>>>(enc, W_enc, b_enc, pred, W_pred, b_pred, W_out);
    joint_tanh_kernel<<<(M_TOTAL * 80) / 256, 256>>>();
    gemm_lm<<<dim3(DV / BN, M_TOTAL / BM), 128, DYN_SMEM>>>(b_out, out);
}